// round 1
// baseline (speedup 1.0000x reference)
#include <cuda_runtime.h>

#define N_MAT   100000
#define N_ELEM  118
#define HID     128
#define NHEADS  8
#define F_MAT   128
#define F_ELEM  64
#define OUT_DIM 64
#define E_EM    1000000
#define E_MM    2000000
#define NEG_SLOPE 0.2f

// ---------------- scratch (static device globals; no allocation) ----------------
__device__ float g_h_mat[(size_t)N_MAT * HID];    // 51.2 MB
__device__ float g_h_elem[N_ELEM * HID];
__device__ float g_as_em[N_ELEM * NHEADS];
__device__ float g_ad_em[N_MAT * NHEADS];
__device__ float g_as_mm[N_MAT * NHEADS];
__device__ float g_ad_mm[N_MAT * NHEADS];
__device__ float g_den_em[N_MAT * NHEADS];
__device__ float g_den_mm[N_MAT * NHEADS];
__device__ float g_o_em[(size_t)N_MAT * HID];     // 51.2 MB
__device__ float g_o_mm[(size_t)N_MAT * HID];     // 51.2 MB
__device__ float g_red[2 * HID];
__device__ float g_attn[2];

// ---------------- zero accumulators ----------------
__global__ void zero_kernel() {
    long i0 = (long)blockIdx.x * blockDim.x + threadIdx.x;
    long nt = (long)gridDim.x * blockDim.x;
    float4 z = make_float4(0.f, 0.f, 0.f, 0.f);
    float4* oe = (float4*)g_o_em;
    float4* om = (float4*)g_o_mm;
    for (long i = i0; i < (long)N_MAT * (HID / 4); i += nt) { oe[i] = z; om[i] = z; }
    float4* de = (float4*)g_den_em;
    float4* dm = (float4*)g_den_mm;
    for (long i = i0; i < (long)N_MAT * (NHEADS / 4); i += nt) { de[i] = z; dm[i] = z; }
    if (i0 < 2 * HID) g_red[i0] = 0.f;
}

// ---------------- projection: mat nodes (F=128), 8 nodes/block ----------------
__global__ void proj_mat_kernel(const float* __restrict__ x, const float* __restrict__ W,
                                const float* __restrict__ b,
                                const float* __restrict__ a_ad_em,
                                const float* __restrict__ a_as_mm,
                                const float* __restrict__ a_ad_mm) {
    __shared__ float xs[8][F_MAT];
    int t = threadIdx.x;              // 0..127 -> output channel
    int n0 = blockIdx.x * 8;
    const float4* xg = (const float4*)(x + (size_t)n0 * F_MAT);
    float4* xs4 = (float4*)&xs[0][0];
    xs4[t] = xg[t];
    xs4[t + 128] = xg[t + 128];
    __syncthreads();

    float acc[8];
#pragma unroll
    for (int i = 0; i < 8; i++) acc[i] = 0.f;
    const float4* Wr = (const float4*)(W + (size_t)t * F_MAT);
#pragma unroll 8
    for (int k4 = 0; k4 < F_MAT / 4; k4++) {
        float4 wv = Wr[k4];
#pragma unroll
        for (int i = 0; i < 8; i++) {
            float4 xv = *(const float4*)&xs[i][k4 * 4];
            acc[i] += wv.x * xv.x + wv.y * xv.y + wv.z * xv.z + wv.w * xv.w;
        }
    }
    float bb = b[t];
    float ae = a_ad_em[t], am1 = a_as_mm[t], am2 = a_ad_mm[t];
    int head = t >> 4;
#pragma unroll
    for (int i = 0; i < 8; i++) {
        float h = acc[i] + bb;
        g_h_mat[(size_t)(n0 + i) * HID + t] = h;
        float v1 = h * ae, v2 = h * am1, v3 = h * am2;
#pragma unroll
        for (int off = 8; off; off >>= 1) {
            v1 += __shfl_down_sync(0xffffffffu, v1, off);
            v2 += __shfl_down_sync(0xffffffffu, v2, off);
            v3 += __shfl_down_sync(0xffffffffu, v3, off);
        }
        if ((t & 15) == 0) {
            g_ad_em[(n0 + i) * NHEADS + head] = v1;
            g_as_mm[(n0 + i) * NHEADS + head] = v2;
            g_ad_mm[(n0 + i) * NHEADS + head] = v3;
        }
    }
}

// ---------------- projection: elem nodes (F=64), 1 node/block ----------------
__global__ void proj_elem_kernel(const float* __restrict__ x, const float* __restrict__ W,
                                 const float* __restrict__ b, const float* __restrict__ a_src) {
    __shared__ float xs[F_ELEM];
    int t = threadIdx.x;   // 0..127
    int n = blockIdx.x;
    if (t < F_ELEM) xs[t] = x[n * F_ELEM + t];
    __syncthreads();
    float acc = b[t];
    const float4* Wr = (const float4*)(W + (size_t)t * F_ELEM);
#pragma unroll
    for (int k4 = 0; k4 < F_ELEM / 4; k4++) {
        float4 wv = Wr[k4];
        float4 xv = *(const float4*)&xs[k4 * 4];
        acc += wv.x * xv.x + wv.y * xv.y + wv.z * xv.z + wv.w * xv.w;
    }
    g_h_elem[n * HID + t] = acc;
    float v = acc * a_src[t];
#pragma unroll
    for (int off = 8; off; off >>= 1) v += __shfl_down_sync(0xffffffffu, v, off);
    if ((t & 15) == 0) g_as_em[n * NHEADS + (t >> 4)] = v;
}

// ---------------- edge pass 1: denominators (no segment_max needed; alpha is tiny) ----------------
__global__ void edge_den_kernel(const int* __restrict__ src, const int* __restrict__ dst,
                                int E, int type) {
    int e = blockIdx.x * blockDim.x + threadIdx.x;
    if (e >= E) return;
    const float* as = type ? g_as_mm : g_as_em;
    const float* ad = type ? g_ad_mm : g_ad_em;
    float* den = type ? g_den_mm : g_den_em;
    int s = src[e], d = dst[e];
    const float4* av = (const float4*)(as + (size_t)s * NHEADS);
    const float4* bv = (const float4*)(ad + (size_t)d * NHEADS);
    float4 a0 = av[0], a1 = av[1], b0 = bv[0], b1 = bv[1];
    float al[8] = {a0.x + b0.x, a0.y + b0.y, a0.z + b0.z, a0.w + b0.w,
                   a1.x + b1.x, a1.y + b1.y, a1.z + b1.z, a1.w + b1.w};
    float ev[8];
#pragma unroll
    for (int h = 0; h < 8; h++) {
        float a = al[h] > 0.f ? al[h] : NEG_SLOPE * al[h];
        ev[h] = __expf(a);
    }
    float* dp = den + (size_t)d * NHEADS;
    asm volatile("red.global.add.v4.f32 [%0], {%1,%2,%3,%4};"
                 :: "l"(dp), "f"(ev[0]), "f"(ev[1]), "f"(ev[2]), "f"(ev[3]) : "memory");
    asm volatile("red.global.add.v4.f32 [%0], {%1,%2,%3,%4};"
                 :: "l"(dp + 4), "f"(ev[4]), "f"(ev[5]), "f"(ev[6]), "f"(ev[7]) : "memory");
}

// ---------------- edge pass 2: weighted aggregation, warp per edge ----------------
__global__ void edge_agg_kernel(const int* __restrict__ src, const int* __restrict__ dst,
                                int E, int type) {
    int gi = blockIdx.x * blockDim.x + threadIdx.x;
    int e = gi >> 5;
    if (e >= E) return;
    int lane = gi & 31;
    const float* as  = type ? g_as_mm : g_as_em;
    const float* ad  = type ? g_ad_mm : g_ad_em;
    const float* den = type ? g_den_mm : g_den_em;
    const float* hs  = type ? g_h_mat : g_h_elem;
    float* outp      = type ? g_o_mm : g_o_em;
    int s = src[e], d = dst[e];
    float w = 0.f;
    if (lane < 8) {
        float a = as[(size_t)s * NHEADS + lane] + ad[(size_t)d * NHEADS + lane];
        a = a > 0.f ? a : NEG_SLOPE * a;
        w = __expf(a) / (den[(size_t)d * NHEADS + lane] + 1e-16f);
    }
    w = __shfl_sync(0xffffffffu, w, lane >> 2);   // head = (4*lane)/16 = lane/4
    float4 v = ((const float4*)(hs + (size_t)s * HID))[lane];
    float* o = outp + (size_t)d * HID + lane * 4;
    asm volatile("red.global.add.v4.f32 [%0], {%1,%2,%3,%4};"
                 :: "l"(o), "f"(v.x * w), "f"(v.y * w), "f"(v.z * w), "f"(v.w * w) : "memory");
}

// ---------------- semantic score: sum_n tanh(relu(o) @ Wk^T + bk), per m ----------------
__global__ void score_kernel(const float* __restrict__ Wk, const float* __restrict__ bk, int m) {
    __shared__ float ss[8][HID];
    int t = threadIdx.x;         // channel c
    int n0 = blockIdx.x * 8;
    const float* o = m ? g_o_mm : g_o_em;
    const float4* og = (const float4*)(o + (size_t)n0 * HID);
    float4* ss4 = (float4*)&ss[0][0];
    float4 v = og[t];
    v.x = fmaxf(v.x, 0.f); v.y = fmaxf(v.y, 0.f); v.z = fmaxf(v.z, 0.f); v.w = fmaxf(v.w, 0.f);
    ss4[t] = v;
    v = og[t + 128];
    v.x = fmaxf(v.x, 0.f); v.y = fmaxf(v.y, 0.f); v.z = fmaxf(v.z, 0.f); v.w = fmaxf(v.w, 0.f);
    ss4[t + 128] = v;
    __syncthreads();

    float acc[8];
#pragma unroll
    for (int i = 0; i < 8; i++) acc[i] = 0.f;
    const float4* Wr = (const float4*)(Wk + (size_t)t * HID);
#pragma unroll 8
    for (int k4 = 0; k4 < HID / 4; k4++) {
        float4 wv = Wr[k4];
#pragma unroll
        for (int i = 0; i < 8; i++) {
            float4 xv = *(const float4*)&ss[i][k4 * 4];
            acc[i] += wv.x * xv.x + wv.y * xv.y + wv.z * xv.z + wv.w * xv.w;
        }
    }
    float bb = bk[t];
    float local = 0.f;
#pragma unroll
    for (int i = 0; i < 8; i++) local += tanhf(acc[i] + bb);
    atomicAdd(&g_red[m * HID + t], local);
}

// ---------------- semantic attention weights (softmax over 2 scores) ----------------
__global__ void attn_kernel(const float* __restrict__ q) {
    int t = threadIdx.x;   // 128 threads
    float qv = q[t];
    float s0 = qv * g_red[t];
    float s1 = qv * g_red[HID + t];
    __shared__ float r0[4], r1[4];
#pragma unroll
    for (int off = 16; off; off >>= 1) {
        s0 += __shfl_down_sync(0xffffffffu, s0, off);
        s1 += __shfl_down_sync(0xffffffffu, s1, off);
    }
    if ((t & 31) == 0) { r0[t >> 5] = s0; r1[t >> 5] = s1; }
    __syncthreads();
    if (t == 0) {
        float a = (r0[0] + r0[1] + r0[2] + r0[3]) * (1.f / N_MAT);
        float b = (r1[0] + r1[1] + r1[2] + r1[3]) * (1.f / N_MAT);
        float mx = fmaxf(a, b);
        float e0 = __expf(a - mx), e1 = __expf(b - mx);
        float inv = 1.f / (e0 + e1);
        g_attn[0] = e0 * inv;
        g_attn[1] = e1 * inv;
    }
}

// ---------------- final: (attn0*relu(o_em) + attn1*relu(o_mm)) @ Wl^T + bl ----------------
__global__ void final_kernel(const float* __restrict__ Wl, const float* __restrict__ bl,
                             float* __restrict__ out) {
    __shared__ float cs[8][HID];
    int t = threadIdx.x;   // 0..63 -> output channel j
    int n0 = blockIdx.x * 8;
    float a0 = g_attn[0], a1 = g_attn[1];
    const float4* eg = (const float4*)(g_o_em + (size_t)n0 * HID);
    const float4* mg = (const float4*)(g_o_mm + (size_t)n0 * HID);
    float4* cs4 = (float4*)&cs[0][0];
#pragma unroll
    for (int r = 0; r < 4; r++) {
        int idx = r * 64 + t;
        float4 e = eg[idx], mm = mg[idx];
        float4 c;
        c.x = a0 * fmaxf(e.x, 0.f) + a1 * fmaxf(mm.x, 0.f);
        c.y = a0 * fmaxf(e.y, 0.f) + a1 * fmaxf(mm.y, 0.f);
        c.z = a0 * fmaxf(e.z, 0.f) + a1 * fmaxf(mm.z, 0.f);
        c.w = a0 * fmaxf(e.w, 0.f) + a1 * fmaxf(mm.w, 0.f);
        cs4[idx] = c;
    }
    __syncthreads();
    float acc[8];
#pragma unroll
    for (int i = 0; i < 8; i++) acc[i] = 0.f;
    const float4* Wr = (const float4*)(Wl + (size_t)t * HID);
#pragma unroll 8
    for (int k4 = 0; k4 < HID / 4; k4++) {
        float4 wv = Wr[k4];
#pragma unroll
        for (int i = 0; i < 8; i++) {
            float4 xv = *(const float4*)&cs[i][k4 * 4];
            acc[i] += wv.x * xv.x + wv.y * xv.y + wv.z * xv.z + wv.w * xv.w;
        }
    }
    float bb = bl[t];
#pragma unroll
    for (int i = 0; i < 8; i++)
        out[(size_t)(n0 + i) * OUT_DIM + t] = acc[i] + bb;
}

// ---------------- launcher ----------------
extern "C" void kernel_launch(void* const* d_in, const int* in_sizes, int n_in,
                              void* d_out, int out_size) {
    const float* x_mat    = (const float*)d_in[0];
    const float* x_elem   = (const float*)d_in[1];
    const float* W_pm     = (const float*)d_in[2];
    const float* b_pm     = (const float*)d_in[3];
    const float* W_pe     = (const float*)d_in[4];
    const float* b_pe     = (const float*)d_in[5];
    const float* a_src_em = (const float*)d_in[6];
    const float* a_dst_em = (const float*)d_in[7];
    const float* a_src_mm = (const float*)d_in[8];
    const float* a_dst_mm = (const float*)d_in[9];
    const float* Wk       = (const float*)d_in[10];
    const float* bk       = (const float*)d_in[11];
    const float* q        = (const float*)d_in[12];
    const float* Wl       = (const float*)d_in[13];
    const float* bl       = (const float*)d_in[14];
    const int* src_em     = (const int*)d_in[15];
    const int* dst_em     = (const int*)d_in[16];
    const int* src_mm     = (const int*)d_in[17];
    const int* dst_mm     = (const int*)d_in[18];
    float* out = (float*)d_out;

    zero_kernel<<<2048, 256>>>();
    proj_elem_kernel<<<N_ELEM, 128>>>(x_elem, W_pe, b_pe, a_src_em);
    proj_mat_kernel<<<N_MAT / 8, 128>>>(x_mat, W_pm, b_pm, a_dst_em, a_src_mm, a_dst_mm);
    edge_den_kernel<<<(E_EM + 255) / 256, 256>>>(src_em, dst_em, E_EM, 0);
    edge_den_kernel<<<(E_MM + 255) / 256, 256>>>(src_mm, dst_mm, E_MM, 1);
    edge_agg_kernel<<<E_EM / 8, 256>>>(src_em, dst_em, E_EM, 0);
    edge_agg_kernel<<<E_MM / 8, 256>>>(src_mm, dst_mm, E_MM, 1);
    score_kernel<<<N_MAT / 8, 128>>>(Wk, bk, 0);
    score_kernel<<<N_MAT / 8, 128>>>(Wk, bk, 1);
    attn_kernel<<<1, 128>>>(q);
    final_kernel<<<N_MAT / 8, 64>>>(Wl, bl, out);
}